// round 5
// baseline (speedup 1.0000x reference)
#include <cuda_runtime.h>
#include <cstdint>

#define BB 512
#define SS 1024
#define TT 64

// scratch (device globals; no allocation allowed)
__device__ float g_fwd[BB];
__device__ float g_gold[BB];

// ---------------- packed f32x2 helpers ----------------
__device__ __forceinline__ unsigned long long pack2(float lo, float hi) {
    unsigned long long r;
    asm("mov.b64 %0, {%1,%2};" : "=l"(r) : "f"(lo), "f"(hi));
    return r;
}
__device__ __forceinline__ void unpack2(unsigned long long v, float& lo, float& hi) {
    asm("mov.b64 {%0,%1}, %2;" : "=f"(lo), "=f"(hi) : "l"(v));
}
__device__ __forceinline__ unsigned long long fma2(unsigned long long a,
                                                   unsigned long long b,
                                                   unsigned long long c) {
    unsigned long long d;
    asm("fma.rn.f32x2 %0, %1, %2, %3;" : "=l"(d) : "l"(a), "l"(b), "l"(c));
    return d;
}
__device__ __forceinline__ unsigned long long add2(unsigned long long a,
                                                   unsigned long long b) {
    unsigned long long d;
    asm("add.rn.f32x2 %0, %1, %2;" : "=l"(d) : "l"(a), "l"(b));
    return d;
}
__device__ __forceinline__ unsigned long long mul2(unsigned long long a,
                                                   unsigned long long b) {
    unsigned long long d;
    asm("mul.rn.f32x2 %0, %1, %2;" : "=l"(d) : "l"(a), "l"(b));
    return d;
}

// ---------------- forward (log-partition) kernel ----------------
// 128 CTAs x 128 threads; warp w handles batch row b = blockIdx.x*4 + w.
// expT column-pair per lane in registers (64 x f32x2).
// alpha kept in per-warp shared memory as duplicated pairs: alpha_sh[..][k]
//   = { pack2(a_{2k},a_{2k}), pack2(a_{2k+1},a_{2k+1}) } for broadcast LDS.128.
__global__ void __launch_bounds__(128, 1)
fwd_kernel(const float* __restrict__ em,
           const float* __restrict__ mask,
           const float* __restrict__ trans) {
    __shared__ ulonglong2 alpha_sh[4][2][32];

    const int lane = threadIdx.x & 31;
    const int wid  = threadIdx.x >> 5;
    const int b    = blockIdx.x * 4 + wid;

    // expT into registers: t[i] = (exp(T[i][2*lane]), exp(T[i][2*lane+1]))
    unsigned long long t[TT];
#pragma unroll
    for (int i = 0; i < TT; i++) {
        float2 tv = *reinterpret_cast<const float2*>(trans + i * TT + 2 * lane);
        t[i] = pack2(__expf(tv.x), __expf(tv.y));
    }

    const float* eb = em + (size_t)b * SS * TT;
    const float* mb = mask + (size_t)b * SS;

    // init: alpha = exp(e0 * m0)
    {
        float  m0 = mb[0];
        float2 e0 = *reinterpret_cast<const float2*>(eb + 2 * lane);
        float a0 = __expf(e0.x * m0);
        float a1 = __expf(e0.y * m0);
        alpha_sh[wid][0][lane] = make_ulonglong2(pack2(a0, a0), pack2(a1, a1));
    }
    __syncwarp();

    float logZ = 0.0f;

    // prefetch emissions 4 steps ahead
    float2 ebuf[4];
    float  mbuf[4];
#pragma unroll
    for (int p = 0; p < 4; p++) {
        int s = 1 + p;
        ebuf[p] = *reinterpret_cast<const float2*>(eb + s * TT + 2 * lane);
        mbuf[p] = mb[s];
    }

    auto step = [&](int sidx, int slot, int bin, int bout, bool resc) {
        const ulonglong2* ain = &alpha_sh[wid][bin][0];
        unsigned long long acc0 = 0ull, acc1 = 0ull;  // packed (0.f,0.f)
#pragma unroll
        for (int k = 0; k < 32; k++) {
            ulonglong2 a = ain[k];
            acc0 = fma2(a.x, t[2 * k],     acc0);
            acc1 = fma2(a.y, t[2 * k + 1], acc1);
        }
        float2 e = ebuf[slot];
        float  m = mbuf[slot];
        int sp = sidx + 4;
        if (sp < SS) {
            ebuf[slot] = *reinterpret_cast<const float2*>(eb + sp * TT + 2 * lane);
            mbuf[slot] = mb[sp];
        }
        unsigned long long beta = add2(acc0, acc1);
        float ex0 = __expf(e.x * m);
        float ex1 = __expf(e.y * m);
        unsigned long long an = mul2(beta, pack2(ex0, ex1));
        float lo, hi;
        unpack2(an, lo, hi);
        if (resc) {
            float v = lo + hi;
            v += __shfl_xor_sync(0xffffffffu, v, 16);
            v += __shfl_xor_sync(0xffffffffu, v, 8);
            v += __shfl_xor_sync(0xffffffffu, v, 4);
            v += __shfl_xor_sync(0xffffffffu, v, 2);
            v += __shfl_xor_sync(0xffffffffu, v, 1);
            float inv = __fdividef(1.0f, v);
            logZ += __logf(v);
            lo *= inv;
            hi *= inv;
        }
        alpha_sh[wid][bout][lane] = make_ulonglong2(pack2(lo, lo), pack2(hi, hi));
        __syncwarp();
    };

    // steps s = 1 .. 1020 in groups of 4 (rescale on the 4th of each group)
    int s = 1;
    for (int g = 0; g < 255; ++g) {
        step(s + 0, 0, 0, 1, false);
        step(s + 1, 1, 1, 0, false);
        step(s + 2, 2, 0, 1, false);
        step(s + 3, 3, 1, 0, true);
        s += 4;
    }
    // tail: s = 1021, 1022, 1023
    step(1021, 0, 0, 1, false);
    step(1022, 1, 1, 0, false);
    step(1023, 2, 0, 1, false);

    // final logsumexp = logZ + log(sum(alpha)); last write went to buffer 1
    {
        ulonglong2 a = alpha_sh[wid][1][lane];
        float lo0, d0, lo1, d1;
        unpack2(a.x, lo0, d0);
        unpack2(a.y, lo1, d1);
        float v = lo0 + lo1;
        v += __shfl_xor_sync(0xffffffffu, v, 16);
        v += __shfl_xor_sync(0xffffffffu, v, 8);
        v += __shfl_xor_sync(0xffffffffu, v, 4);
        v += __shfl_xor_sync(0xffffffffu, v, 2);
        v += __shfl_xor_sync(0xffffffffu, v, 1);
        if (lane == 0) g_fwd[b] = logZ + __logf(v);
    }
}

// ---------------- gold score kernel ----------------
__global__ void gold_kernel(const float* __restrict__ em,
                            const int* __restrict__ tags,
                            const float* __restrict__ mask,
                            const float* __restrict__ trans) {
    const int b   = blockIdx.x;
    const int tid = threadIdx.x;
    const int*   tg = tags + (size_t)b * SS;
    const float* mb = mask + (size_t)b * SS;
    const float* eb = em + (size_t)b * SS * TT;

    float acc = 0.0f;
    for (int s = tid; s < SS; s += 256) {
        int   cur = tg[s];
        float m   = mb[s];
        float e   = eb[s * TT + cur];
        float c;
        if (s == 0) {
            c = e * m;
        } else {
            int prev = tg[s - 1];
            c = (trans[cur * TT + prev] + e) * m;  // transitions[curr, prev]
        }
        acc += c;
    }
    __shared__ float sh[256];
    sh[tid] = acc;
    __syncthreads();
    for (int o = 128; o > 0; o >>= 1) {
        if (tid < o) sh[tid] += sh[tid + o];
        __syncthreads();
    }
    if (tid == 0) g_gold[b] = sh[0];
}

// ---------------- final mean(fwd - gold) ----------------
__global__ void reduce_kernel(float* __restrict__ out) {
    const int tid = threadIdx.x;
    __shared__ float sh[BB];
    sh[tid] = g_fwd[tid] - g_gold[tid];
    __syncthreads();
    for (int o = BB / 2; o > 0; o >>= 1) {
        if (tid < o) sh[tid] += sh[tid + o];
        __syncthreads();
    }
    if (tid == 0) out[0] = sh[0] * (1.0f / (float)BB);
}

extern "C" void kernel_launch(void* const* d_in, const int* in_sizes, int n_in,
                              void* d_out, int out_size) {
    const float* emissions   = (const float*)d_in[0];  // (B,S,T) f32
    const int*   tags        = (const int*)d_in[1];    // (B,S)   i32
    const float* mask        = (const float*)d_in[2];  // (B,S)   f32
    const float* transitions = (const float*)d_in[3];  // (T,T)   f32
    float* out = (float*)d_out;

    fwd_kernel<<<BB / 4, 128>>>(emissions, mask, transitions);
    gold_kernel<<<BB, 256>>>(emissions, tags, mask, transitions);
    reduce_kernel<<<1, BB>>>(out);
}

// round 8
// speedup vs baseline: 1.0268x; 1.0268x over previous
#include <cuda_runtime.h>
#include <cstdint>

#define BB 512
#define SS 1024
#define TT 64

// scratch (device globals; no allocation allowed)
__device__ float g_fwd[BB];
__device__ float g_gold[BB];

// ---------------- packed f32x2 helpers ----------------
__device__ __forceinline__ unsigned long long pack2(float lo, float hi) {
    unsigned long long r;
    asm("mov.b64 %0, {%1,%2};" : "=l"(r) : "f"(lo), "f"(hi));
    return r;
}
__device__ __forceinline__ void unpack2(unsigned long long v, float& lo, float& hi) {
    asm("mov.b64 {%0,%1}, %2;" : "=f"(lo), "=f"(hi) : "l"(v));
}
__device__ __forceinline__ unsigned long long fma2(unsigned long long a,
                                                   unsigned long long b,
                                                   unsigned long long c) {
    unsigned long long d;
    asm("fma.rn.f32x2 %0, %1, %2, %3;" : "=l"(d) : "l"(a), "l"(b), "l"(c));
    return d;
}
__device__ __forceinline__ unsigned long long add2(unsigned long long a,
                                                   unsigned long long b) {
    unsigned long long d;
    asm("add.rn.f32x2 %0, %1, %2;" : "=l"(d) : "l"(a), "l"(b));
    return d;
}

#define ROW_BAR() asm volatile("bar.sync %0, 64;" :: "r"(barid) : "memory")

// ---------------- forward (log-partition) kernel ----------------
// 128 CTAs x 256 threads. Each batch row is handled by TWO warps:
//   warp half h computes output states [32h, 32h+32), one state per lane.
// alpha lives in per-row shared float[64] (double buffered); the f32x2
// pair layout over inputs equals natural float order, so writes are STS.32
// and reads are broadcast LDS.128 (ulonglong2 = 2 input pairs).
// expT column j (packed by input pairs) lives in 32 u64 registers per lane.
__global__ void __launch_bounds__(256, 1)
fwd_kernel(const float* __restrict__ em,
           const float* __restrict__ mask,
           const float* __restrict__ trans) {
    __shared__ __align__(16) float alpha_sh[4][2][TT];  // [row][buf][state]
    __shared__ float tbuf[TT * TT];                     // staged transitions
    __shared__ float partial[4][2];                     // rescale partials

    const int tid  = threadIdx.x;
    const int lane = tid & 31;
    const int wid  = tid >> 5;    // 0..7
    const int row  = wid >> 1;    // 0..3  (row within CTA)
    const int half = wid & 1;     // 0..1  (which output half)
    const int b    = blockIdx.x * 4 + row;
    const int j    = lane + 32 * half;  // this lane's output state
    const int barid = 1 + row;

    // stage transitions coalesced, then build exp'd column j packed by
    // input pairs: tcol[k] = (exp(T[2k][j]), exp(T[2k+1][j]))
    for (int i = tid; i < TT * TT; i += 256) tbuf[i] = trans[i];
    __syncthreads();

    unsigned long long tcol[32];
#pragma unroll
    for (int k = 0; k < 32; k++) {
        float a = __expf(tbuf[(2 * k) * TT + j]);
        float c = __expf(tbuf[(2 * k + 1) * TT + j]);
        tcol[k] = pack2(a, c);
    }

    const float* eb = em + (size_t)b * SS * TT;
    const float* mb = mask + (size_t)b * SS;

    // init: alpha = exp(e0 * m0)
    alpha_sh[row][0][j] = __expf(eb[j] * mb[0]);
    __syncthreads();  // covers tbuf reuse + init visibility for all rows

    float logZ = 0.0f;

    // prefetch emissions 4 steps ahead (scalar per lane: state j)
    float ebuf[4];
    float mbuf[4];
#pragma unroll
    for (int p = 0; p < 4; p++) {
        ebuf[p] = eb[(1 + p) * TT + j];
        mbuf[p] = mb[1 + p];
    }

    auto step = [&](int sidx, int slot, int bin, int bout, bool resc) {
        const ulonglong2* ain =
            reinterpret_cast<const ulonglong2*>(&alpha_sh[row][bin][0]);
        unsigned long long acc0 = 0ull, acc1 = 0ull;
#pragma unroll
        for (int k = 0; k < 16; k++) {
            ulonglong2 a = ain[k];                    // alpha[4k..4k+3]
            acc0 = fma2(a.x, tcol[2 * k + 0], acc0);  // pairs (4k,4k+1)
            acc1 = fma2(a.y, tcol[2 * k + 1], acc1);  // pairs (4k+2,4k+3)
        }
        float e = ebuf[slot];
        float m = mbuf[slot];
        int sp = sidx + 4;
        if (sp < SS) {
            ebuf[slot] = eb[sp * TT + j];
            mbuf[slot] = mb[sp];
        }
        float lo, hi;
        unpack2(add2(acc0, acc1), lo, hi);
        float y = (lo + hi) * __expf(e * m);
        if (resc) {
            float v = y;
            v += __shfl_xor_sync(0xffffffffu, v, 16);
            v += __shfl_xor_sync(0xffffffffu, v, 8);
            v += __shfl_xor_sync(0xffffffffu, v, 4);
            v += __shfl_xor_sync(0xffffffffu, v, 2);
            v += __shfl_xor_sync(0xffffffffu, v, 1);
            if (lane == 0) partial[row][half] = v;
            ROW_BAR();
            float vv = partial[row][0] + partial[row][1];
            logZ += __logf(vv);
            y *= __fdividef(1.0f, vv);
        }
        alpha_sh[row][bout][j] = y;
        ROW_BAR();  // drains STS; next step may read bout
    };

    // steps s = 1 .. 1020 in groups of 4 (rescale on the 4th of each group)
    int s = 1;
    for (int g = 0; g < 255; ++g) {
        step(s + 0, 0, 0, 1, false);
        step(s + 1, 1, 1, 0, false);
        step(s + 2, 2, 0, 1, false);
        step(s + 3, 3, 1, 0, true);
        s += 4;
    }
    // tail: s = 1021, 1022, 1023 (last write lands in buffer 1)
    step(1021, 0, 0, 1, false);
    step(1022, 1, 1, 0, false);
    step(1023, 2, 0, 1, false);

    // final logsumexp = logZ + log(sum(alpha))
    {
        float v = alpha_sh[row][1][j];
        v += __shfl_xor_sync(0xffffffffu, v, 16);
        v += __shfl_xor_sync(0xffffffffu, v, 8);
        v += __shfl_xor_sync(0xffffffffu, v, 4);
        v += __shfl_xor_sync(0xffffffffu, v, 2);
        v += __shfl_xor_sync(0xffffffffu, v, 1);
        if (lane == 0) partial[row][half] = v;
        ROW_BAR();
        if (half == 0 && lane == 0) {
            g_fwd[b] = logZ + __logf(partial[row][0] + partial[row][1]);
        }
    }
}

// ---------------- gold score kernel ----------------
__global__ void gold_kernel(const float* __restrict__ em,
                            const int* __restrict__ tags,
                            const float* __restrict__ mask,
                            const float* __restrict__ trans) {
    const int b   = blockIdx.x;
    const int tid = threadIdx.x;
    const int*   tg = tags + (size_t)b * SS;
    const float* mb = mask + (size_t)b * SS;
    const float* eb = em + (size_t)b * SS * TT;

    float acc = 0.0f;
    for (int s = tid; s < SS; s += 256) {
        int   cur = tg[s];
        float m   = mb[s];
        float e   = eb[s * TT + cur];
        float c;
        if (s == 0) {
            c = e * m;
        } else {
            int prev = tg[s - 1];
            c = (trans[cur * TT + prev] + e) * m;  // transitions[curr, prev]
        }
        acc += c;
    }
    __shared__ float sh[256];
    sh[tid] = acc;
    __syncthreads();
    for (int o = 128; o > 0; o >>= 1) {
        if (tid < o) sh[tid] += sh[tid + o];
        __syncthreads();
    }
    if (tid == 0) g_gold[b] = sh[0];
}

// ---------------- final mean(fwd - gold) ----------------
__global__ void reduce_kernel(float* __restrict__ out) {
    const int tid = threadIdx.x;
    __shared__ float sh[BB];
    sh[tid] = g_fwd[tid] - g_gold[tid];
    __syncthreads();
    for (int o = BB / 2; o > 0; o >>= 1) {
        if (tid < o) sh[tid] += sh[tid + o];
        __syncthreads();
    }
    if (tid == 0) out[0] = sh[0] * (1.0f / (float)BB);
}

extern "C" void kernel_launch(void* const* d_in, const int* in_sizes, int n_in,
                              void* d_out, int out_size) {
    const float* emissions   = (const float*)d_in[0];  // (B,S,T) f32
    const int*   tags        = (const int*)d_in[1];    // (B,S)   i32
    const float* mask        = (const float*)d_in[2];  // (B,S)   f32
    const float* transitions = (const float*)d_in[3];  // (T,T)   f32
    float* out = (float*)d_out;

    fwd_kernel<<<BB / 4, 256>>>(emissions, mask, transitions);
    gold_kernel<<<BB, 256>>>(emissions, tags, mask, transitions);
    reduce_kernel<<<1, BB>>>(out);
}